// round 11
// baseline (speedup 1.0000x reference)
#include <cuda_runtime.h>
#include <cuda_bf16.h>
#include <cstdint>

// YOLO head decode: (B, 3*85, 52, 52) -> (B, 3*52*52, 85)
//   c==0: (sigmoid(v)+gx)*stride
//   c==1: (sigmoid(v)+gy)*stride
//   c==2: exp(v)*anchor_w      (stride cancels)
//   c==3: exp(v)*anchor_h
//   c>=4: sigmoid(v)
//
// R11: DRAM-efficiency fix on top of the R10 MLP=5 design.
//   2-row tile (104 positions): every per-channel read segment is 416B at a
//   32B-aligned offset = exactly 13 sectors, ZERO overfetch (1-row tiles had
//   208B segments alternating 16B-misaligned -> ~7.7% read overfetch).
//   512 threads, 5 front-batched predicated LDG.128 slots (same in-flight
//   bytes/SM as R10), __launch_bounds__(512,3) caps regs at 42.
//   Store: one cp.async.bulk of 35360B (smem is in flat output order).

#define G       52
#define GG      2704        // 52*52
#define GG4     676         // GG/4
#define NCH     85
#define NA      3
#define TILE    104         // 2 grid rows
#define NT4     26          // TILE/4 float4s per channel segment
#define TPP     26          // tiles per plane (2704/104)
#define NMAIN   2106        // 81 sigmoid channels * 26 float4s
#define NSLOT   5           // ceil(2106/512)
#define TOUT    8840        // 104*85 floats per tile (= smem = out slice)
#define TBYTES  35360       // TOUT*4, multiple of 16
#define THREADS 512

__device__ __forceinline__ float fsig(float v) {
    // 1/(1+exp(-v)) via fast exp + rcp; inputs ~N(0,1), no overflow risk
    return __fdividef(1.0f, 1.0f + __expf(-v));
}

__global__ __launch_bounds__(THREADS, 3)
void yolo_decode_kernel(const float* __restrict__ x,
                        const void* __restrict__ img_raw,
                        float* __restrict__ out)
{
    __shared__ __align__(16) float s[TOUT];

    const int tid   = threadIdx.x;
    const int tile  = blockIdx.x % TPP;   // covers grid rows 2*tile, 2*tile+1
    const int plane = blockIdx.x / TPP;   // b*3 + a
    const int a     = plane % NA;

    // ---- decode img_dim scalar; tolerate missing input or unknown dtype ----
    float img = 416.0f;
    if (img_raw != nullptr) {
        const int lo = *(const int*)img_raw;
        if (lo >= 1 && lo <= 1000000) {
            img = (float)lo;                              // int32 / int64 low word
        } else {
            const float f = __int_as_float(lo);
            if (f >= 1.f && f <= 1.e6f) img = f;          // float32
        }
    }
    const float stride = img * (1.f / (float)G);
    const int   gy0    = tile * 2;

    const int base4 = (plane * (NCH * GG) + tile * TILE) >> 2;
    const float4* __restrict__ in4 = (const float4*)x;

    // ================= FRONT-BATCHED LOADS (max MLP) =================

    // prologue load: special channels 0..3 (104 float4s), tid < 104
    float4 pv;
    const bool has_pro = (tid < 4 * NT4);
    const int pc  = tid / NT4;            // 0..3 (meaningful only if has_pro)
    const int pp4 = tid - pc * NT4;
    if (has_pro) {
        pv = in4[base4 + pc * GG4 + pp4];
    }

    // main loads: channels 4..84, 5 predicated slots, issued back-to-back
    float4 v[NSLOT];
    #pragma unroll
    for (int k = 0; k < NSLOT; k++) {
        const int i = tid + k * THREADS;
        if (i < NMAIN) {
            const int q = i / NT4;        // const-div -> mulhi, cheap
            v[k] = in4[base4 + (4 + q) * GG4 + (i - q * NT4)];
        }
    }

    // ================= COMPUTE + STS =================

    if (has_pro) {
        const int pos = pp4 << 2;         // position within tile, 0..100
        const float aw = (a == 0) ? 10.f : (a == 1) ? 16.f : 33.f;
        const float ah = (a == 0) ? 13.f : (a == 1) ? 30.f : 23.f;
        float r[4] = {pv.x, pv.y, pv.z, pv.w};
        #pragma unroll
        for (int j = 0; j < 4; j++) {
            const float val = r[j];
            const int p = pos + j;        // 0..103
            const int row2 = (p >= G) ? 1 : 0;
            float o;
            if (pc == 0)      o = (fsig(val) + (float)(p - row2 * G)) * stride;
            else if (pc == 1) o = (fsig(val) + (float)(gy0 + row2)) * stride;
            else if (pc == 2) o = __expf(val) * aw;
            else              o = __expf(val) * ah;
            s[p * NCH + pc] = o;
        }
    }

    #pragma unroll
    for (int k = 0; k < NSLOT; k++) {
        const int i = tid + k * THREADS;
        if (i < NMAIN) {
            const int q  = i / NT4;       // recomputed (cheaper than live regs)
            const int c  = 4 + q;
            const int p4 = i - q * NT4;
            float* sp = s + (p4 << 2) * NCH + c;   // (p,c) at p*85+c
            sp[0 * NCH] = fsig(v[k].x);
            sp[1 * NCH] = fsig(v[k].y);
            sp[2 * NCH] = fsig(v[k].z);
            sp[3 * NCH] = fsig(v[k].w);
        }
    }

    __syncthreads();

    // ---- store: single TMA bulk copy smem -> gmem (no store loop) ----
    if (tid == 0) {
        float* gptr = out + (size_t)plane * (GG * NCH) + (size_t)tile * TOUT;
        uint32_t saddr;
        asm("{ .reg .u64 t; cvta.to.shared.u64 t, %1; cvt.u32.u64 %0, t; }"
            : "=r"(saddr) : "l"(s));
        asm volatile("fence.proxy.async.shared::cta;" ::: "memory");
        asm volatile(
            "cp.async.bulk.global.shared::cta.bulk_group [%0], [%1], %2;"
            :: "l"(gptr), "r"(saddr), "r"(TBYTES) : "memory");
        asm volatile("cp.async.bulk.commit_group;" ::: "memory");
        // Ensure the bulk engine has finished READING smem before block exit.
        asm volatile("cp.async.bulk.wait_group 0;" ::: "memory");
    }
}

extern "C" void kernel_launch(void* const* d_in, const int* in_sizes, int n_in,
                              void* d_out, int out_size)
{
    const float* x = (const float*)d_in[0];
    const void* img = (n_in >= 2 && in_sizes[1] >= 1) ? d_in[1] : nullptr;
    float* out = (float*)d_out;

    int B = in_sizes[0] / (NA * NCH * GG);
    if (B <= 0) B = out_size / (NA * GG * NCH);
    const int grid = B * NA * TPP;               // 4992 blocks @ B=64

    yolo_decode_kernel<<<grid, THREADS>>>(x, img, out);
}